// round 12
// baseline (speedup 1.0000x reference)
#include <cuda_runtime.h>
#include <cuda_bf16.h>

#define NN 50000
#define EE 800000
#define ET (EE + NN)
#define BB 64
#define D_IN 3
#define D_HID 128
#define D_LAT 64
#define N_CLS 2
#define NB_SCAN ((NN + 1023) / 1024)

// ---------------- scratch (device globals; no allocation allowed) -----------
__device__ float g_bufA[NN * D_HID];
__device__ float g_bufB[NN * D_HID];
__device__ float g_hs[NN];
__device__ float g_hd[NN];
__device__ int   g_rowptr[NN + 1];
__device__ int   g_cursor[NN];
__device__ int   g_csrc[ET];
__device__ int   g_part[64];
__device__ float g_pooled[BB * D_LAT];
__device__ float g_cnt[BB];
__device__ int   g_ei64;   // 1 if edge_index buffer is int64, 0 if int32
__device__ int   g_b64;    // 1 if batch buffer is int64, 0 if int32

// ---------------- helpers ---------------------------------------------------
__device__ __forceinline__ float warpSum(float v) {
    #pragma unroll
    for (int o = 16; o; o >>= 1) v += __shfl_xor_sync(0xFFFFFFFFu, v, o);
    return v;
}
__device__ __forceinline__ float warpMax(float v) {
    #pragma unroll
    for (int o = 16; o; o >>= 1) v = fmaxf(v, __shfl_xor_sync(0xFFFFFFFFu, v, o));
    return v;
}
__device__ __forceinline__ int loadIdx(const void* p, long long i, int is64) {
    return is64 ? (int)((const long long*)p)[i] : ((const int*)p)[i];
}
// Clamped index load: if dtype detection is ever wrong, produce a finite wrong
// answer (rel_err signal) instead of an OOB crash (no signal). When detection
// is right — the expected case — indices are already in range and the clamp
// is a no-op (one IMNMX hidden under the memory latency these loops eat).
__device__ __forceinline__ int loadIdxClamp(const void* p, long long i, int is64, int hi) {
    int v = loadIdx(p, i, is64);
    return min(max(v, 0), hi - 1);
}
__device__ __forceinline__ float leaky(float e) {
    return (e > 0.f) ? e : 0.2f * e;
}

// ---------------- dtype detection (both buffers, one launch) -----------------
// edge_index: values uniform in [0, NN). Probe first 64 int64 slots: a real
// int32 buffer packs two values per slot -> nonzero high word w.h.p.
// batch: SORTED values in [0, B) — the front is all zeros (would fool a front
// probe), so probe int64 slots just below NN/2: in-bounds under either dtype;
// under int32 those slots pack late (~B-1) values in the high word -> huge.
__global__ void k_detect(const void* pe, const void* pb) {
    if (threadIdx.x == 0) {
        const long long* q = (const long long*)pe;
        int ok = 1;
        for (int i = 0; i < 64; i++) {
            long long v = q[i];
            if (v < 0 || v >= NN) { ok = 0; break; }
        }
        g_ei64 = ok;
    } else if (threadIdx.x == 32) {
        const long long* q = (const long long*)pb;
        int ok = 1;
        for (int i = NN / 2 - 64; i < NN / 2; i++) {
            long long v = q[i];
            if (v < 0 || v >= NN) { ok = 0; break; }
        }
        g_b64 = ok;
    }
}

// ---------------- CSR build (+ pooled-buffer zeroing folded in) --------------
__global__ void k_deg_init(int n) {
    int i = blockIdx.x * blockDim.x + threadIdx.x;
    if (i < n) g_cursor[i] = 1;  // self loop
    if (i < BB * D_LAT) g_pooled[i] = 0.f;
    if (i < BB) g_cnt[i] = 0.f;
}

// ei layout: send = elements [0, EE), recv = elements [EE, 2*EE)
__global__ void k_deg_count(const void* __restrict__ ei, int e) {
    int i = blockIdx.x * blockDim.x + threadIdx.x;
    int is64 = g_ei64;
    if (i < e) atomicAdd(&g_cursor[loadIdxClamp(ei, (long long)EE + i, is64, NN)], 1);
}

__global__ void k_scan1(int n) {
    __shared__ int s[1024];
    int gid = blockIdx.x * 1024 + threadIdx.x;
    int v = (gid < n) ? g_cursor[gid] : 0;
    s[threadIdx.x] = v;
    __syncthreads();
    #pragma unroll
    for (int off = 1; off < 1024; off <<= 1) {
        int t = (threadIdx.x >= off) ? s[threadIdx.x - off] : 0;
        __syncthreads();
        s[threadIdx.x] += t;
        __syncthreads();
    }
    if (gid < n) g_rowptr[gid] = s[threadIdx.x] - v;  // block-local exclusive
    if (threadIdx.x == 1023) g_part[blockIdx.x] = s[1023];
}

__global__ void k_scan2(int nb, int ntot, int etot) {
    if (threadIdx.x == 0 && blockIdx.x == 0) {
        int sum = 0;
        for (int b = 0; b < nb; b++) { int t = g_part[b]; g_part[b] = sum; sum += t; }
        g_rowptr[ntot] = etot;
    }
}

__global__ void k_scan3(int n) {
    int gid = blockIdx.x * blockDim.x + threadIdx.x;
    if (gid < n) {
        int v = g_rowptr[gid] + g_part[gid >> 10];
        g_rowptr[gid] = v;
        g_cursor[gid] = v;
    }
}

__global__ void k_fill(const void* __restrict__ ei, int e, int n) {
    int i = blockIdx.x * blockDim.x + threadIdx.x;
    int is64 = g_ei64;
    if (i < e) {
        int r = loadIdxClamp(ei, (long long)EE + i, is64, NN);
        int pos = atomicAdd(&g_cursor[r], 1);
        g_csrc[min(pos, ET - 1)] = loadIdxClamp(ei, i, is64, NN);
    } else if (i < e + n) {
        int node = i - e;
        int pos = atomicAdd(&g_cursor[node], 1);
        g_csrc[min(pos, ET - 1)] = node;
    }
}

// ---------------- fused h = x @ W  +  hs = h@a_src, hd = h@a_dst -------------
// blockDim.x must equal DOUT; each thread owns one output column for NPB nodes.
template <int DIN, int DOUT, int NPB>
__global__ void k_gemm_fused(const float* __restrict__ x, const float* __restrict__ W,
                             const float* __restrict__ as, const float* __restrict__ ad,
                             float* __restrict__ h, int n) {
    __shared__ float sW[DIN * DOUT];
    __shared__ float sx[NPB * DIN];
    __shared__ float sred[2][NPB][DOUT / 32];
    int tid = threadIdx.x;
    for (int i = tid; i < DIN * DOUT; i += DOUT) sW[i] = W[i];
    int node0 = blockIdx.x * NPB;
    for (int i = tid; i < NPB * DIN; i += DOUT) {
        int node = node0 + i / DIN;
        sx[i] = (node < n) ? x[node * DIN + (i % DIN)] : 0.f;
    }
    __syncthreads();

    const int c = tid;
    float asv = as[c], adv = ad[c];
    float acc[NPB];
    #pragma unroll
    for (int l = 0; l < NPB; l++) acc[l] = 0.f;
    #pragma unroll 4
    for (int k = 0; k < DIN; k++) {
        float w = sW[k * DOUT + c];
        #pragma unroll
        for (int l = 0; l < NPB; l++) acc[l] += sx[l * DIN + k] * w;
    }
    int lane = tid & 31, wrp = tid >> 5;
    #pragma unroll
    for (int l = 0; l < NPB; l++) {
        int node = node0 + l;
        if (node < n) h[node * DOUT + c] = acc[l];
        float ps = warpSum(acc[l] * asv);
        float pd = warpSum(acc[l] * adv);
        if (lane == 0) { sred[0][l][wrp] = ps; sred[1][l][wrp] = pd; }
    }
    __syncthreads();
    if (tid < 2 * NPB) {
        int kind = tid & 1, l = tid >> 1;
        int node = node0 + l;
        if (node < n) {
            float s = 0.f;
            #pragma unroll
            for (int w = 0; w < DOUT / 32; w++) s += sred[kind][l][w];
            if (kind == 0) g_hs[node] = s; else g_hd[node] = s;
        }
    }
}

// ---------------- fused layer-4 GEMM (128 -> 3) + attention scalars ----------
__global__ void k_gemm3_scal(const float* __restrict__ x, const float* __restrict__ W,
                             const float* __restrict__ as, const float* __restrict__ ad,
                             float* __restrict__ h, int n) {
    __shared__ float sW[D_HID * 3];
    int tid = threadIdx.x;
    for (int i = tid; i < D_HID * 3; i += blockDim.x) sW[i] = W[i];
    __syncthreads();

    int node = (blockIdx.x * blockDim.x + tid) >> 5;
    int lane = tid & 31;
    if (node >= n) return;

    float4 v = reinterpret_cast<const float4*>(x)[node * 32 + lane];
    int k0 = lane * 4;
    float p0 = v.x * sW[k0 * 3 + 0] + v.y * sW[(k0 + 1) * 3 + 0]
             + v.z * sW[(k0 + 2) * 3 + 0] + v.w * sW[(k0 + 3) * 3 + 0];
    float p1 = v.x * sW[k0 * 3 + 1] + v.y * sW[(k0 + 1) * 3 + 1]
             + v.z * sW[(k0 + 2) * 3 + 1] + v.w * sW[(k0 + 3) * 3 + 1];
    float p2 = v.x * sW[k0 * 3 + 2] + v.y * sW[(k0 + 1) * 3 + 2]
             + v.z * sW[(k0 + 2) * 3 + 2] + v.w * sW[(k0 + 3) * 3 + 2];
    p0 = warpSum(p0);
    p1 = warpSum(p1);
    p2 = warpSum(p2);
    if (lane < 3) {
        float hv = (lane == 0) ? p0 : (lane == 1) ? p1 : p2;
        h[node * 3 + lane] = hv;
    }
    if (lane == 0) {
        g_hs[node] = p0 * as[0] + p1 * as[1] + p2 * as[2];
        g_hd[node] = p0 * ad[0] + p1 * ad[1] + p2 * ad[2];
    }
}

// ---------------- GAT aggregation (warp per destination node) ---------------
// deg<=32 fast path (99.97% of nodes at mean degree 17): single chunk, e/exp
// computed ONCE per edge, (src,alpha) kept in-register for the broadcast loop.
template <int DOUT, bool RELU>
__global__ void k_agg(const float* __restrict__ h, const float* __restrict__ bias,
                      float* __restrict__ out, int n) {
    int wid = (blockIdx.x * blockDim.x + threadIdx.x) >> 5;
    int lane = threadIdx.x & 31;
    if (wid >= n) return;
    int beg = g_rowptr[wid], end = g_rowptr[wid + 1];
    int deg = end - beg;
    float hdn = g_hd[wid];

    int srcR = 0; float alphaR = 0.f;   // per-lane edge data (fast path)
    float m, inv;
    bool fast = (deg <= 32);
    if (fast) {
        bool valid = lane < deg;
        srcR = valid ? g_csrc[beg + lane] : 0;
        float e = valid ? leaky(g_hs[srcR] + hdn) : -1e30f;
        m = warpMax(e);
        float ex = valid ? __expf(e - m) : 0.f;
        float s = warpSum(ex);
        inv = 1.f / s;
        alphaR = ex * inv;
    } else {
        m = -1e30f;
        for (int i = beg + lane; i < end; i += 32)
            m = fmaxf(m, leaky(g_hs[g_csrc[i]] + hdn));
        m = warpMax(m);
        float s = 0.f;
        for (int i = beg + lane; i < end; i += 32)
            s += __expf(leaky(g_hs[g_csrc[i]] + hdn) - m);
        s = warpSum(s);
        inv = 1.f / s;
    }

    if constexpr (DOUT == 128) {
        const float4* __restrict__ h4 = reinterpret_cast<const float4*>(h);
        float4 acc = make_float4(0.f, 0.f, 0.f, 0.f);
        for (int i0 = beg; i0 < end; i0 += 32) {
            int src = srcR; float alpha = alphaR;
            if (!fast) {
                int i = i0 + lane;
                src = 0; alpha = 0.f;
                if (i < end) {
                    src = g_csrc[i];
                    alpha = __expf(leaky(g_hs[src] + hdn) - m) * inv;
                }
            }
            int cnt = min(32, end - i0);
            #pragma unroll 4
            for (int k = 0; k < cnt; k++) {
                float a = __shfl_sync(0xFFFFFFFFu, alpha, k);
                int sx = __shfl_sync(0xFFFFFFFFu, src, k);
                float4 v = h4[sx * 32 + lane];
                acc.x += a * v.x; acc.y += a * v.y;
                acc.z += a * v.z; acc.w += a * v.w;
            }
        }
        float4 bv = reinterpret_cast<const float4*>(bias)[lane];
        acc.x += bv.x; acc.y += bv.y; acc.z += bv.z; acc.w += bv.w;
        if (RELU) {
            acc.x = fmaxf(acc.x, 0.f); acc.y = fmaxf(acc.y, 0.f);
            acc.z = fmaxf(acc.z, 0.f); acc.w = fmaxf(acc.w, 0.f);
        }
        reinterpret_cast<float4*>(out)[wid * 32 + lane] = acc;
    } else if constexpr (DOUT == 64) {
        const float2* __restrict__ h2 = reinterpret_cast<const float2*>(h);
        float2 acc = make_float2(0.f, 0.f);
        for (int i0 = beg; i0 < end; i0 += 32) {
            int src = srcR; float alpha = alphaR;
            if (!fast) {
                int i = i0 + lane;
                src = 0; alpha = 0.f;
                if (i < end) {
                    src = g_csrc[i];
                    alpha = __expf(leaky(g_hs[src] + hdn) - m) * inv;
                }
            }
            int cnt = min(32, end - i0);
            #pragma unroll 4
            for (int k = 0; k < cnt; k++) {
                float a = __shfl_sync(0xFFFFFFFFu, alpha, k);
                int sx = __shfl_sync(0xFFFFFFFFu, src, k);
                float2 v = h2[sx * 32 + lane];
                acc.x += a * v.x; acc.y += a * v.y;
            }
        }
        float2 bv = reinterpret_cast<const float2*>(bias)[lane];
        acc.x += bv.x; acc.y += bv.y;
        if (RELU) { acc.x = fmaxf(acc.x, 0.f); acc.y = fmaxf(acc.y, 0.f); }
        reinterpret_cast<float2*>(out)[wid * 32 + lane] = acc;
    } else {
        float acc = 0.f;
        for (int i0 = beg; i0 < end; i0 += 32) {
            int src = srcR; float alpha = alphaR;
            if (!fast) {
                int i = i0 + lane;
                src = 0; alpha = 0.f;
                if (i < end) {
                    src = g_csrc[i];
                    alpha = __expf(leaky(g_hs[src] + hdn) - m) * inv;
                }
            }
            int cnt = min(32, end - i0);
            #pragma unroll 4
            for (int k = 0; k < cnt; k++) {
                float a = __shfl_sync(0xFFFFFFFFu, alpha, k);
                int sx = __shfl_sync(0xFFFFFFFFu, src, k);
                if (lane < DOUT) acc += a * h[sx * DOUT + lane];
            }
        }
        if (lane < DOUT) {
            float v = acc + bias[lane];
            if (RELU) v = fmaxf(v, 0.f);
            out[wid * DOUT + lane] = v;
        }
    }
}

// ---------------- pooling + head --------------------------------------------
// Run-based pooling: batch is SORTED, so each thread owns one column over a
// run of RUN consecutive nodes, accumulating in-register and flushing one
// atomic per distinct batch id in the run (almost always exactly one).
#define POOL_RUN 8
__global__ void k_pool(const float* __restrict__ latent,
                       const void* __restrict__ batch, int n) {
    int idx = blockIdx.x * blockDim.x + threadIdx.x;
    int run = idx >> 6;              // run index
    int c = idx & 63;                // column
    int node0 = run * POOL_RUN;
    if (node0 >= n) return;
    int is64 = g_b64;
    int nodeEnd = min(node0 + POOL_RUN, n);

    int curB = loadIdxClamp(batch, node0, is64, BB);
    float acc = 0.f;
    float cnt = 0.f;
    for (int node = node0; node < nodeEnd; node++) {
        int b = loadIdxClamp(batch, node, is64, BB);
        if (b != curB) {
            atomicAdd(&g_pooled[curB * D_LAT + c], acc);
            if (c == 0) atomicAdd(&g_cnt[curB], cnt);
            curB = b; acc = 0.f; cnt = 0.f;
        }
        acc += latent[node * D_LAT + c];
        cnt += 1.f;
    }
    atomicAdd(&g_pooled[curB * D_LAT + c], acc);
    if (c == 0) atomicAdd(&g_cnt[curB], cnt);
}

__global__ void k_head(const float* __restrict__ Wc1, const float* __restrict__ bc1,
                       const float* __restrict__ Wc2, const float* __restrict__ bc2,
                       float* __restrict__ out) {
    __shared__ float pm[BB * D_LAT];
    __shared__ float z[BB * (D_LAT / 2)];
    int tid = threadIdx.x;
    for (int i = tid; i < BB * D_LAT; i += blockDim.x) {
        int g = i >> 6;
        pm[i] = g_pooled[i] / fmaxf(g_cnt[g], 1.f);
    }
    __syncthreads();
    for (int i = tid; i < BB * (D_LAT / 2); i += blockDim.x) {
        int g = i >> 5, j = i & 31;
        float a = bc1[j];
        for (int k = 0; k < D_LAT; k++) a += pm[g * D_LAT + k] * Wc1[k * (D_LAT / 2) + j];
        z[i] = fmaxf(a, 0.f);
    }
    __syncthreads();
    for (int i = tid; i < BB * N_CLS; i += blockDim.x) {
        int g = i >> 1, t = i & 1;
        float a = bc2[t];
        for (int j = 0; j < D_LAT / 2; j++) a += z[g * (D_LAT / 2) + j] * Wc2[j * N_CLS + t];
        out[i] = a;
    }
}

// ---------------- launcher ---------------------------------------------------
extern "C" void kernel_launch(void* const* d_in, const int* in_sizes, int n_in,
                              void* d_out, int out_size) {
    const float* x = (const float*)d_in[0];
    const void* ei = d_in[1];       // int64 or int32, detected on device
    const void* batch = d_in[2];    // int64 or int32, detected on device
    const float* W1 = (const float*)d_in[3];
    const float* a1s = (const float*)d_in[4];
    const float* a1d = (const float*)d_in[5];
    const float* b1 = (const float*)d_in[6];
    const float* W2 = (const float*)d_in[7];
    const float* a2s = (const float*)d_in[8];
    const float* a2d = (const float*)d_in[9];
    const float* b2 = (const float*)d_in[10];
    const float* W3 = (const float*)d_in[11];
    const float* a3s = (const float*)d_in[12];
    const float* a3d = (const float*)d_in[13];
    const float* b3 = (const float*)d_in[14];
    const float* W4 = (const float*)d_in[15];
    const float* a4s = (const float*)d_in[16];
    const float* a4d = (const float*)d_in[17];
    const float* b4 = (const float*)d_in[18];
    const float* Wc1 = (const float*)d_in[19];
    const float* bc1 = (const float*)d_in[20];
    const float* Wc2 = (const float*)d_in[21];
    const float* bc2 = (const float*)d_in[22];

    float* out = (float*)d_out;
    float* recon = out;                   // [N, 3]
    float* latent = out + NN * D_IN;      // [N, 64]
    float* noise = latent + NN * D_LAT;   // [B, 2]

    float* bufA;
    float* bufB;
    cudaGetSymbolAddress((void**)&bufA, g_bufA);
    cudaGetSymbolAddress((void**)&bufB, g_bufB);

    // --- index dtype detection (graph-capturable, deterministic) ---
    k_detect<<<1, 64>>>(ei, batch);

    // --- CSR by destination (k_deg_init also zeroes pooling buffers) ---
    k_deg_init<<<(NN + 255) / 256, 256>>>(NN);
    k_deg_count<<<(EE + 255) / 256, 256>>>(ei, EE);
    k_scan1<<<NB_SCAN, 1024>>>(NN);
    k_scan2<<<1, 32>>>(NB_SCAN, NN, ET);
    k_scan3<<<(NN + 255) / 256, 256>>>(NN);
    k_fill<<<(ET + 255) / 256, 256>>>(ei, EE, NN);

    const int WPB = 8;
    int warpGrid = (NN + WPB - 1) / WPB;

    // --- layer 1: x[N,3] -> relu(gat) [N,128] in bufA ---
    k_gemm_fused<D_IN, D_HID, 8><<<(NN + 7) / 8, D_HID>>>(x, W1, a1s, a1d, bufB, NN);
    k_agg<D_HID, true><<<warpGrid, WPB * 32>>>(bufB, b1, bufA, NN);

    // --- layer 2: bufA -> latent [N,64] (no relu); NPB=16 halves W traffic ---
    k_gemm_fused<D_HID, D_LAT, 16><<<(NN + 15) / 16, D_LAT>>>(bufA, W2, a2s, a2d, bufB, NN);
    k_agg<D_LAT, false><<<warpGrid, WPB * 32>>>(bufB, b2, latent, NN);

    // --- layer 3: latent -> relu(gat) [N,128] in bufA; NPB=16 ---
    k_gemm_fused<D_LAT, D_HID, 16><<<(NN + 15) / 16, D_HID>>>(latent, W3, a3s, a3d, bufB, NN);
    k_agg<D_HID, true><<<warpGrid, WPB * 32>>>(bufB, b3, bufA, NN);

    // --- layer 4: bufA -> reconstructed [N,3] (no relu), fused gemm+scal ---
    k_gemm3_scal<<<warpGrid, WPB * 32>>>(bufA, W4, a4s, a4d, bufB, NN);
    k_agg<D_IN, false><<<warpGrid, WPB * 32>>>(bufB, b4, recon, NN);

    // --- pooling + classifier head ---
    {
        int runs = (NN + POOL_RUN - 1) / POOL_RUN;
        long long thr = (long long)runs * 64;
        k_pool<<<(int)((thr + 255) / 256), 256>>>(latent, batch, NN);
    }
    k_head<<<1, 256>>>(Wc1, bc1, Wc2, bc2, noise);
}

// round 13
// speedup vs baseline: 1.0363x; 1.0363x over previous
#include <cuda_runtime.h>
#include <cuda_bf16.h>

#define NN 50000
#define EE 800000
#define ET (EE + NN)
#define BB 64
#define D_IN 3
#define D_HID 128
#define D_LAT 64
#define N_CLS 2
#define NB_SCAN ((NN + 1023) / 1024)
#define WARPS 16   // warps per block in fused agg+gemm kernels

// ---------------- scratch (device globals; no allocation allowed) -----------
__device__ float g_bufA[NN * D_HID];
__device__ float g_bufB[NN * D_HID];
__device__ float g_hs[NN];
__device__ float g_hd[NN];
__device__ float g_hs2[NN];
__device__ float g_hd2[NN];
__device__ int   g_rowptr[NN + 1];
__device__ int   g_cursor[NN];
__device__ int   g_csrc[ET];
__device__ int   g_part[64];
__device__ float g_pooled[BB * D_LAT];
__device__ float g_cnt[BB];
__device__ int   g_ei64;
__device__ int   g_b64;

// ---------------- helpers ---------------------------------------------------
__device__ __forceinline__ float warpSum(float v) {
    #pragma unroll
    for (int o = 16; o; o >>= 1) v += __shfl_xor_sync(0xFFFFFFFFu, v, o);
    return v;
}
__device__ __forceinline__ float warpMax(float v) {
    #pragma unroll
    for (int o = 16; o; o >>= 1) v = fmaxf(v, __shfl_xor_sync(0xFFFFFFFFu, v, o));
    return v;
}
__device__ __forceinline__ int loadIdx(const void* p, long long i, int is64) {
    return is64 ? (int)((const long long*)p)[i] : ((const int*)p)[i];
}
__device__ __forceinline__ int loadIdxClamp(const void* p, long long i, int is64, int hi) {
    int v = loadIdx(p, i, is64);
    return min(max(v, 0), hi - 1);
}
__device__ __forceinline__ float leaky(float e) {
    return (e > 0.f) ? e : 0.2f * e;
}

// ---------------- init + parallel dtype detection (one launch) ---------------
// edge_index: uniform [0,NN) — front int64 probe; int32 packing -> nonzero high
// word w.h.p. batch: SORTED (front all zeros!), probe slots just below NN/2.
__global__ void k_deg_init(const void* pe, const void* pb, int n) {
    int i = blockIdx.x * blockDim.x + threadIdx.x;
    if (i < n) g_cursor[i] = 1;  // self loop
    if (i < BB * D_LAT) g_pooled[i] = 0.f;
    if (i < BB) g_cnt[i] = 0.f;
    if (blockIdx.x == 0 && threadIdx.x < 64) {
        int lane = threadIdx.x & 31;
        if (threadIdx.x < 32) {
            const long long* q = (const long long*)pe;
            long long v0 = q[lane], v1 = q[32 + lane];
            bool ok = (v0 >= 0 && v0 < NN && v1 >= 0 && v1 < NN);
            unsigned all = __all_sync(0xFFFFFFFFu, ok);
            if (lane == 0) g_ei64 = all ? 1 : 0;
        } else {
            const long long* q = (const long long*)pb;
            long long v0 = q[NN / 2 - 64 + lane], v1 = q[NN / 2 - 32 + lane];
            bool ok = (v0 >= 0 && v0 < NN && v1 >= 0 && v1 < NN);
            unsigned all = __all_sync(0xFFFFFFFFu, ok);
            if (lane == 0) g_b64 = all ? 1 : 0;
        }
    }
}

// ---------------- CSR build --------------------------------------------------
__global__ void k_deg_count(const void* __restrict__ ei, int e) {
    int i = blockIdx.x * blockDim.x + threadIdx.x;
    int is64 = g_ei64;
    if (i < e) atomicAdd(&g_cursor[loadIdxClamp(ei, (long long)EE + i, is64, NN)], 1);
}

// warp-shuffle block scan (2 barriers instead of 20)
__global__ void k_scan1(int n) {
    __shared__ int wsum[32];
    int tid = threadIdx.x, lane = tid & 31, wr = tid >> 5;
    int gid = blockIdx.x * 1024 + tid;
    int v = (gid < n) ? g_cursor[gid] : 0;
    int x = v;
    #pragma unroll
    for (int o = 1; o < 32; o <<= 1) {
        int t = __shfl_up_sync(0xFFFFFFFFu, x, o);
        if (lane >= o) x += t;
    }
    if (lane == 31) wsum[wr] = x;
    __syncthreads();
    if (wr == 0) {
        int y = wsum[lane];
        #pragma unroll
        for (int o = 1; o < 32; o <<= 1) {
            int t = __shfl_up_sync(0xFFFFFFFFu, y, o);
            if (lane >= o) y += t;
        }
        wsum[lane] = y;
    }
    __syncthreads();
    int base = wr ? wsum[wr - 1] : 0;
    int incl = x + base;
    if (gid < n) g_rowptr[gid] = incl - v;  // exclusive
    if (tid == 1023) g_part[blockIdx.x] = incl;
}

__global__ void k_scan2(int nb, int ntot, int etot) {
    if (threadIdx.x == 0 && blockIdx.x == 0) {
        int sum = 0;
        for (int b = 0; b < nb; b++) { int t = g_part[b]; g_part[b] = sum; sum += t; }
        g_rowptr[ntot] = etot;
    }
}

__global__ void k_scan3(int n) {
    int gid = blockIdx.x * blockDim.x + threadIdx.x;
    if (gid < n) {
        int v = g_rowptr[gid] + g_part[gid >> 10];
        g_rowptr[gid] = v;
        g_cursor[gid] = v;
    }
}

__global__ void k_fill(const void* __restrict__ ei, int e, int n) {
    int i = blockIdx.x * blockDim.x + threadIdx.x;
    int is64 = g_ei64;
    if (i < e) {
        int r = loadIdxClamp(ei, (long long)EE + i, is64, NN);
        int pos = atomicAdd(&g_cursor[r], 1);
        g_csrc[min(pos, ET - 1)] = loadIdxClamp(ei, i, is64, NN);
    } else if (i < e + n) {
        int node = i - e;
        int pos = atomicAdd(&g_cursor[node], 1);
        g_csrc[min(pos, ET - 1)] = node;
    }
}

// ---------------- layer-1 GEMM (3 -> 128) + attention scalars ----------------
template <int DIN, int DOUT, int NPB>
__global__ void k_gemm_fused(const float* __restrict__ x, const float* __restrict__ W,
                             const float* __restrict__ as, const float* __restrict__ ad,
                             float* __restrict__ h,
                             float* __restrict__ hs_out, float* __restrict__ hd_out, int n) {
    __shared__ float sW[DIN * DOUT];
    __shared__ float sx[NPB * DIN];
    __shared__ float sred[2][NPB][DOUT / 32];
    int tid = threadIdx.x;
    for (int i = tid; i < DIN * DOUT; i += DOUT) sW[i] = W[i];
    int node0 = blockIdx.x * NPB;
    for (int i = tid; i < NPB * DIN; i += DOUT) {
        int node = node0 + i / DIN;
        sx[i] = (node < n) ? x[node * DIN + (i % DIN)] : 0.f;
    }
    __syncthreads();

    const int c = tid;
    float asv = as[c], adv = ad[c];
    float acc[NPB];
    #pragma unroll
    for (int l = 0; l < NPB; l++) acc[l] = 0.f;
    #pragma unroll 4
    for (int k = 0; k < DIN; k++) {
        float w = sW[k * DOUT + c];
        #pragma unroll
        for (int l = 0; l < NPB; l++) acc[l] += sx[l * DIN + k] * w;
    }
    int lane = tid & 31, wrp = tid >> 5;
    #pragma unroll
    for (int l = 0; l < NPB; l++) {
        int node = node0 + l;
        if (node < n) h[node * DOUT + c] = acc[l];
        float ps = warpSum(acc[l] * asv);
        float pd = warpSum(acc[l] * adv);
        if (lane == 0) { sred[0][l][wrp] = ps; sred[1][l][wrp] = pd; }
    }
    __syncthreads();
    if (tid < 2 * NPB) {
        int kind = tid & 1, l = tid >> 1;
        int node = node0 + l;
        if (node < n) {
            float s = 0.f;
            #pragma unroll
            for (int w = 0; w < DOUT / 32; w++) s += sred[kind][l][w];
            if (kind == 0) hs_out[node] = s; else hd_out[node] = s;
        }
    }
}

// ---------------- FUSED: GAT aggregation + next-layer GEMM -------------------
// Phase A (warp per node): softmax-weighted aggregation over incoming edges of
// hin rows (DIN wide) + bias (+relu). Optionally writes the layer output.
// Phase B (block-cooperative): h' = rows @ Wn (DIN x DOUT) + next-layer
// attention scalars, written to hout / hs_out / hd_out.
// DOUT==3 specialization: per-warp epilogue, no phase B.
template <int DIN, int DOUT, bool RELU, bool WRITE_OUT>
__global__ __launch_bounds__(WARPS * 32)
void k_agg_gemm(const float* __restrict__ hin, const float* __restrict__ bias,
                const float* __restrict__ hs_in, const float* __restrict__ hd_in,
                float* __restrict__ outp,
                const float* __restrict__ Wn, const float* __restrict__ asn,
                const float* __restrict__ adn,
                float* __restrict__ hout, float* __restrict__ hs_out,
                float* __restrict__ hd_out, int n) {
    __shared__ float sW[DIN * DOUT];
    __shared__ __align__(16) float sx[WARPS][DIN];
    __shared__ float sred[2][WARPS][(DOUT >= 32) ? (DOUT / 32) : 1];

    int tid = threadIdx.x, lane = tid & 31, wr = tid >> 5;
    for (int i = tid; i < DIN * DOUT; i += WARPS * 32) sW[i] = Wn[i];
    __syncthreads();

    int node = blockIdx.x * WARPS + wr;
    bool activeN = (node < n);

    // ---- Phase A: aggregation (warp-uniform activity) ----
    int beg = 0, end = 0, deg = 0;
    float hdn = 0.f;
    if (activeN) {
        beg = g_rowptr[node];
        end = g_rowptr[node + 1];
        deg = end - beg;
        hdn = hd_in[node];
    }
    int srcR = 0; float alphaR = 0.f;
    float m = 0.f, inv = 0.f;
    bool fast = (deg <= 32);
    if (activeN) {
        if (fast) {
            bool valid = lane < deg;
            srcR = valid ? g_csrc[beg + lane] : 0;
            float e = valid ? leaky(hs_in[srcR] + hdn) : -1e30f;
            m = warpMax(e);
            float ex = valid ? __expf(e - m) : 0.f;
            float s = warpSum(ex);
            inv = 1.f / s;
            alphaR = ex * inv;
        } else {
            m = -1e30f;
            for (int i = beg + lane; i < end; i += 32)
                m = fmaxf(m, leaky(hs_in[g_csrc[i]] + hdn));
            m = warpMax(m);
            float s = 0.f;
            for (int i = beg + lane; i < end; i += 32)
                s += __expf(leaky(hs_in[g_csrc[i]] + hdn) - m);
            s = warpSum(s);
            inv = 1.f / s;
        }
    }

    if constexpr (DIN == 128) {
        float4 acc = make_float4(0.f, 0.f, 0.f, 0.f);
        if (activeN) {
            const float4* __restrict__ h4 = reinterpret_cast<const float4*>(hin);
            for (int i0 = beg; i0 < end; i0 += 32) {
                int src = srcR; float alpha = alphaR;
                if (!fast) {
                    int i = i0 + lane;
                    src = 0; alpha = 0.f;
                    if (i < end) {
                        src = g_csrc[i];
                        alpha = __expf(leaky(hs_in[src] + hdn) - m) * inv;
                    }
                }
                int cnt = min(32, end - i0);
                #pragma unroll 4
                for (int k = 0; k < cnt; k++) {
                    float a = __shfl_sync(0xFFFFFFFFu, alpha, k);
                    int sxi = __shfl_sync(0xFFFFFFFFu, src, k);
                    float4 v = h4[sxi * 32 + lane];
                    acc.x += a * v.x; acc.y += a * v.y;
                    acc.z += a * v.z; acc.w += a * v.w;
                }
            }
            float4 bv = reinterpret_cast<const float4*>(bias)[lane];
            acc.x += bv.x; acc.y += bv.y; acc.z += bv.z; acc.w += bv.w;
            if (RELU) {
                acc.x = fmaxf(acc.x, 0.f); acc.y = fmaxf(acc.y, 0.f);
                acc.z = fmaxf(acc.z, 0.f); acc.w = fmaxf(acc.w, 0.f);
            }
            if (WRITE_OUT) reinterpret_cast<float4*>(outp)[node * 32 + lane] = acc;
        }
        if constexpr (DOUT == 3) {
            // per-warp epilogue: 3 dot products + scalars; sW already loaded
            float p0 = acc.x * sW[(4 * lane + 0) * 3 + 0] + acc.y * sW[(4 * lane + 1) * 3 + 0]
                     + acc.z * sW[(4 * lane + 2) * 3 + 0] + acc.w * sW[(4 * lane + 3) * 3 + 0];
            float p1 = acc.x * sW[(4 * lane + 0) * 3 + 1] + acc.y * sW[(4 * lane + 1) * 3 + 1]
                     + acc.z * sW[(4 * lane + 2) * 3 + 1] + acc.w * sW[(4 * lane + 3) * 3 + 1];
            float p2 = acc.x * sW[(4 * lane + 0) * 3 + 2] + acc.y * sW[(4 * lane + 1) * 3 + 2]
                     + acc.z * sW[(4 * lane + 2) * 3 + 2] + acc.w * sW[(4 * lane + 3) * 3 + 2];
            p0 = warpSum(p0); p1 = warpSum(p1); p2 = warpSum(p2);
            if (activeN && lane == 0) {
                hout[node * 3 + 0] = p0;
                hout[node * 3 + 1] = p1;
                hout[node * 3 + 2] = p2;
                hs_out[node] = p0 * asn[0] + p1 * asn[1] + p2 * asn[2];
                hd_out[node] = p0 * adn[0] + p1 * adn[1] + p2 * adn[2];
            }
            return;
        } else {
            if (activeN) reinterpret_cast<float4*>(sx[wr])[lane] = acc;
        }
    } else {  // DIN == 64
        float2 acc = make_float2(0.f, 0.f);
        if (activeN) {
            const float2* __restrict__ h2 = reinterpret_cast<const float2*>(hin);
            for (int i0 = beg; i0 < end; i0 += 32) {
                int src = srcR; float alpha = alphaR;
                if (!fast) {
                    int i = i0 + lane;
                    src = 0; alpha = 0.f;
                    if (i < end) {
                        src = g_csrc[i];
                        alpha = __expf(leaky(hs_in[src] + hdn) - m) * inv;
                    }
                }
                int cnt = min(32, end - i0);
                #pragma unroll 4
                for (int k = 0; k < cnt; k++) {
                    float a = __shfl_sync(0xFFFFFFFFu, alpha, k);
                    int sxi = __shfl_sync(0xFFFFFFFFu, src, k);
                    float2 v = h2[sxi * 32 + lane];
                    acc.x += a * v.x; acc.y += a * v.y;
                }
            }
            float2 bv = reinterpret_cast<const float2*>(bias)[lane];
            acc.x += bv.x; acc.y += bv.y;
            if (RELU) { acc.x = fmaxf(acc.x, 0.f); acc.y = fmaxf(acc.y, 0.f); }
            if (WRITE_OUT) reinterpret_cast<float2*>(outp)[node * 32 + lane] = acc;
            reinterpret_cast<float2*>(sx[wr])[lane] = acc;
        }
    }

    __syncthreads();

    // ---- Phase B: block-cooperative GEMM rows @ Wn + scalars ----
    if constexpr (DOUT != 3) {
        constexpr int CS = (WARPS * 32) / DOUT;   // col-sets
        constexpr int NPT = WARPS / CS;           // nodes per thread
        constexpr int WPS = DOUT / 32;            // warps per col-set
        int c = tid % DOUT;
        int g = tid / DOUT;
        float av = asn[c], dv = adn[c];
        float acc[NPT];
        #pragma unroll
        for (int j = 0; j < NPT; j++) acc[j] = 0.f;
        #pragma unroll 4
        for (int k = 0; k < DIN; k++) {
            float w = sW[k * DOUT + c];
            #pragma unroll
            for (int j = 0; j < NPT; j++) acc[j] += sx[g + j * CS][k] * w;
        }
        int wslot = (tid % DOUT) / 32;
        #pragma unroll
        for (int j = 0; j < NPT; j++) {
            int l = g + j * CS;
            int nd = blockIdx.x * WARPS + l;
            if (nd < n) hout[nd * DOUT + c] = acc[j];
            float ps = warpSum(acc[j] * av);
            float pd = warpSum(acc[j] * dv);
            if (lane == 0) { sred[0][l][wslot] = ps; sred[1][l][wslot] = pd; }
        }
        __syncthreads();
        if (tid < 2 * WARPS) {
            int kind = tid & 1, l = tid >> 1;
            int nd = blockIdx.x * WARPS + l;
            if (nd < n) {
                float s = 0.f;
                #pragma unroll
                for (int w = 0; w < WPS; w++) s += sred[kind][l][w];
                if (kind == 0) hs_out[nd] = s; else hd_out[nd] = s;
            }
        }
    }
}

// ---------------- final GAT aggregation (DOUT=3, writes recon) ---------------
__global__ void k_agg3(const float* __restrict__ h, const float* __restrict__ bias,
                       const float* __restrict__ hs_in, const float* __restrict__ hd_in,
                       float* __restrict__ out, int n) {
    int wid = (blockIdx.x * blockDim.x + threadIdx.x) >> 5;
    int lane = threadIdx.x & 31;
    if (wid >= n) return;
    int beg = g_rowptr[wid], end = g_rowptr[wid + 1];
    int deg = end - beg;
    float hdn = hd_in[wid];

    int srcR = 0; float alphaR = 0.f;
    float m, inv;
    bool fast = (deg <= 32);
    if (fast) {
        bool valid = lane < deg;
        srcR = valid ? g_csrc[beg + lane] : 0;
        float e = valid ? leaky(hs_in[srcR] + hdn) : -1e30f;
        m = warpMax(e);
        float ex = valid ? __expf(e - m) : 0.f;
        float s = warpSum(ex);
        inv = 1.f / s;
        alphaR = ex * inv;
    } else {
        m = -1e30f;
        for (int i = beg + lane; i < end; i += 32)
            m = fmaxf(m, leaky(hs_in[g_csrc[i]] + hdn));
        m = warpMax(m);
        float s = 0.f;
        for (int i = beg + lane; i < end; i += 32)
            s += __expf(leaky(hs_in[g_csrc[i]] + hdn) - m);
        s = warpSum(s);
        inv = 1.f / s;
    }

    float acc = 0.f;
    for (int i0 = beg; i0 < end; i0 += 32) {
        int src = srcR; float alpha = alphaR;
        if (!fast) {
            int i = i0 + lane;
            src = 0; alpha = 0.f;
            if (i < end) {
                src = g_csrc[i];
                alpha = __expf(leaky(hs_in[src] + hdn) - m) * inv;
            }
        }
        int cnt = min(32, end - i0);
        #pragma unroll 4
        for (int k = 0; k < cnt; k++) {
            float a = __shfl_sync(0xFFFFFFFFu, alpha, k);
            int sx = __shfl_sync(0xFFFFFFFFu, src, k);
            if (lane < 3) acc += a * h[sx * 3 + lane];
        }
    }
    if (lane < 3) out[wid * 3 + lane] = acc + bias[lane];
}

// ---------------- pooling + head --------------------------------------------
#define POOL_RUN 8
__global__ void k_pool(const float* __restrict__ latent,
                       const void* __restrict__ batch, int n) {
    int idx = blockIdx.x * blockDim.x + threadIdx.x;
    int run = idx >> 6;
    int c = idx & 63;
    int node0 = run * POOL_RUN;
    if (node0 >= n) return;
    int is64 = g_b64;
    int nodeEnd = min(node0 + POOL_RUN, n);

    int curB = loadIdxClamp(batch, node0, is64, BB);
    float acc = 0.f;
    float cnt = 0.f;
    for (int node = node0; node < nodeEnd; node++) {
        int b = loadIdxClamp(batch, node, is64, BB);
        if (b != curB) {
            atomicAdd(&g_pooled[curB * D_LAT + c], acc);
            if (c == 0) atomicAdd(&g_cnt[curB], cnt);
            curB = b; acc = 0.f; cnt = 0.f;
        }
        acc += latent[node * D_LAT + c];
        cnt += 1.f;
    }
    atomicAdd(&g_pooled[curB * D_LAT + c], acc);
    if (c == 0) atomicAdd(&g_cnt[curB], cnt);
}

__global__ void k_head(const float* __restrict__ Wc1, const float* __restrict__ bc1,
                       const float* __restrict__ Wc2, const float* __restrict__ bc2,
                       float* __restrict__ out) {
    __shared__ float pm[BB * D_LAT];
    __shared__ float z[BB * (D_LAT / 2)];
    int tid = threadIdx.x;
    for (int i = tid; i < BB * D_LAT; i += blockDim.x) {
        int g = i >> 6;
        pm[i] = g_pooled[i] / fmaxf(g_cnt[g], 1.f);
    }
    __syncthreads();
    for (int i = tid; i < BB * (D_LAT / 2); i += blockDim.x) {
        int g = i >> 5, j = i & 31;
        float a = bc1[j];
        for (int k = 0; k < D_LAT; k++) a += pm[g * D_LAT + k] * Wc1[k * (D_LAT / 2) + j];
        z[i] = fmaxf(a, 0.f);
    }
    __syncthreads();
    for (int i = tid; i < BB * N_CLS; i += blockDim.x) {
        int g = i >> 1, t = i & 1;
        float a = bc2[t];
        for (int j = 0; j < D_LAT / 2; j++) a += z[g * (D_LAT / 2) + j] * Wc2[j * N_CLS + t];
        out[i] = a;
    }
}

// ---------------- launcher ---------------------------------------------------
extern "C" void kernel_launch(void* const* d_in, const int* in_sizes, int n_in,
                              void* d_out, int out_size) {
    const float* x = (const float*)d_in[0];
    const void* ei = d_in[1];
    const void* batch = d_in[2];
    const float* W1 = (const float*)d_in[3];
    const float* a1s = (const float*)d_in[4];
    const float* a1d = (const float*)d_in[5];
    const float* b1 = (const float*)d_in[6];
    const float* W2 = (const float*)d_in[7];
    const float* a2s = (const float*)d_in[8];
    const float* a2d = (const float*)d_in[9];
    const float* b2 = (const float*)d_in[10];
    const float* W3 = (const float*)d_in[11];
    const float* a3s = (const float*)d_in[12];
    const float* a3d = (const float*)d_in[13];
    const float* b3 = (const float*)d_in[14];
    const float* W4 = (const float*)d_in[15];
    const float* a4s = (const float*)d_in[16];
    const float* a4d = (const float*)d_in[17];
    const float* b4 = (const float*)d_in[18];
    const float* Wc1 = (const float*)d_in[19];
    const float* bc1 = (const float*)d_in[20];
    const float* Wc2 = (const float*)d_in[21];
    const float* bc2 = (const float*)d_in[22];

    float* out = (float*)d_out;
    float* recon = out;                   // [N, 3]
    float* latent = out + NN * D_IN;      // [N, 64]
    float* noise = latent + NN * D_LAT;   // [B, 2]

    float *bufA, *bufB, *hsA, *hdA, *hsB, *hdB;
    cudaGetSymbolAddress((void**)&bufA, g_bufA);
    cudaGetSymbolAddress((void**)&bufB, g_bufB);
    cudaGetSymbolAddress((void**)&hsA, g_hs);
    cudaGetSymbolAddress((void**)&hdA, g_hd);
    cudaGetSymbolAddress((void**)&hsB, g_hs2);
    cudaGetSymbolAddress((void**)&hdB, g_hd2);

    // --- init (+dtype detect) + CSR build ---
    k_deg_init<<<(NN + 255) / 256, 256>>>(ei, batch, NN);
    k_deg_count<<<(EE + 255) / 256, 256>>>(ei, EE);
    k_scan1<<<NB_SCAN, 1024>>>(NN);
    k_scan2<<<1, 32>>>(NB_SCAN, NN, ET);
    k_scan3<<<(NN + 255) / 256, 256>>>(NN);
    k_fill<<<(ET + 255) / 256, 256>>>(ei, EE, NN);

    int fusedGrid = (NN + WARPS - 1) / WARPS;

    // layer-1 GEMM: x -> h1 (bufB) + scalars (hsA/hdA)
    k_gemm_fused<D_IN, D_HID, 8><<<(NN + 7) / 8, D_HID>>>(x, W1, a1s, a1d, bufB, hsA, hdA, NN);

    // agg1 (relu) fused with GEMM2: h1 -> h2 (bufA) + scalars (hsB/hdB); layer-1 out not needed
    k_agg_gemm<D_HID, D_LAT, true, false><<<fusedGrid, WARPS * 32>>>(
        bufB, b1, hsA, hdA, nullptr, W2, a2s, a2d, bufA, hsB, hdB, NN);

    // agg2 (no relu) writes latent, fused with GEMM3: h2 -> h3 (bufB) + scalars (hsA/hdA)
    k_agg_gemm<D_LAT, D_HID, false, true><<<fusedGrid, WARPS * 32>>>(
        bufA, b2, hsB, hdB, latent, W3, a3s, a3d, bufB, hsA, hdA, NN);

    // agg3 (relu) fused with GEMM4 (128->3): h3 -> h4 (bufA) + scalars (hsB/hdB)
    k_agg_gemm<D_HID, D_IN, true, false><<<fusedGrid, WARPS * 32>>>(
        bufB, b3, hsA, hdA, nullptr, W4, a4s, a4d, bufA, hsB, hdB, NN);

    // final aggregation -> recon
    {
        const int WPB = 8;
        int warpGrid = (NN + WPB - 1) / WPB;
        k_agg3<<<warpGrid, WPB * 32>>>(bufA, b4, hsB, hdB, recon, NN);
    }

    // pooling + classifier head
    {
        int runs = (NN + POOL_RUN - 1) / POOL_RUN;
        long long thr = (long long)runs * 64;
        k_pool<<<(int)((thr + 255) / 256), 256>>>(latent, batch, NN);
    }
    k_head<<<1, 256>>>(Wc1, bc1, Wc2, bc2, noise);
}